// round 7
// baseline (speedup 1.0000x reference)
#include <cuda_runtime.h>

#define D 128
#define MAX_NODES 50048
#define MAX_E     1048576
#define BK 32
#define SAP 132

// Scratch (allocation-free rule: __device__ globals)
__device__ float g_fp[MAX_NODES * D];      // F' = feature @ W^T
__device__ int   g_count[MAX_NODES];
__device__ int   g_start[MAX_NODES + 1];
__device__ int   g_cursor[MAX_NODES];
__device__ int2  g_edges[MAX_E];           // packed {src, w_bits} binned by dst

// ---------------------------------------------------------------------------
// zero per-node edge counts
// ---------------------------------------------------------------------------
__global__ void zero_count_kernel(int N) {
    int i = blockIdx.x * blockDim.x + threadIdx.x;
    if (i < N) g_count[i] = 0;
}

// ---------------------------------------------------------------------------
// histogram of dst (1 edge/thread, coalesced)
// ---------------------------------------------------------------------------
__global__ void hist_kernel(const int* __restrict__ dst, int E) {
    int e = blockIdx.x * blockDim.x + threadIdx.x;
    if (e < E) atomicAdd(&g_count[dst[e]], 1);
}

// ---------------------------------------------------------------------------
// exclusive prefix scan over g_count (single block, 1024 threads)
// ---------------------------------------------------------------------------
__global__ void scan_kernel(int N) {
    __shared__ int part[1024];
    int t = threadIdx.x;
    int chunk = (N + 1023) >> 10;
    int lo = t * chunk;
    int hi = lo + chunk; if (hi > N) hi = N;
    if (lo > N) lo = N;

    int s = 0;
    for (int i = lo; i < hi; i++) s += g_count[i];
    part[t] = s;
    __syncthreads();

    for (int off = 1; off < 1024; off <<= 1) {
        int v = part[t];
        int u = (t >= off) ? part[t - off] : 0;
        __syncthreads();
        part[t] = v + u;
        __syncthreads();
    }

    int run = (t == 0) ? 0 : part[t - 1];
    for (int i = lo; i < hi; i++) {
        int c = g_count[i];
        g_start[i]  = run;
        g_cursor[i] = run;
        run += c;
    }
    if (t == 1023) g_start[N] = part[1023];
}

// ---------------------------------------------------------------------------
// permute: write packed {src, w} into dst-ordered bins
// ---------------------------------------------------------------------------
__global__ void permute_kernel(const int* __restrict__ src,
                               const int* __restrict__ dst,
                               const float* __restrict__ w,
                               int E) {
    int e = blockIdx.x * blockDim.x + threadIdx.x;
    if (e < E) {
        int pos = atomicAdd(&g_cursor[dst[e]], 1);
        g_edges[pos] = make_int2(src[e], __float_as_int(w[e]));
    }
}

// ---------------------------------------------------------------------------
// GEMM: g_fp = feature @ W^T  (fp32 SIMT, 8x8 microtile) — runs on side
// stream, concurrent with the binning chain.
// ---------------------------------------------------------------------------
__global__ void gemm_kernel(const float* __restrict__ A,
                            const float* __restrict__ Wm,
                            int M) {
    __shared__ float sA[BK * SAP];
    __shared__ float sW[BK * SAP];

    int tid = threadIdx.x;
    int tx = tid & 15;
    int ty = tid >> 4;
    int br = blockIdx.x * 128;

    float acc[8][8];
#pragma unroll
    for (int i = 0; i < 8; i++)
#pragma unroll
        for (int j = 0; j < 8; j++) acc[i][j] = 0.f;

    for (int kt = 0; kt < D; kt += BK) {
#pragma unroll
        for (int it = 0; it < 4; it++) {
            int idx4 = tid + it * 256;
            int m  = idx4 >> 3;
            int k  = (idx4 & 7) * 4;

            float4 va = make_float4(0.f, 0.f, 0.f, 0.f);
            if (br + m < M)
                va = *(const float4*)(A + (size_t)(br + m) * D + kt + k);
            sA[(k + 0) * SAP + m] = va.x;
            sA[(k + 1) * SAP + m] = va.y;
            sA[(k + 2) * SAP + m] = va.z;
            sA[(k + 3) * SAP + m] = va.w;

            float4 vw = *(const float4*)(Wm + m * D + kt + k);
            sW[(k + 0) * SAP + m] = vw.x;
            sW[(k + 1) * SAP + m] = vw.y;
            sW[(k + 2) * SAP + m] = vw.z;
            sW[(k + 3) * SAP + m] = vw.w;
        }
        __syncthreads();

#pragma unroll
        for (int k = 0; k < BK; k++) {
            float a[8], wr[8];
            *(float4*)(a)      = *(const float4*)&sA[k * SAP + ty * 8];
            *(float4*)(a + 4)  = *(const float4*)&sA[k * SAP + ty * 8 + 4];
            *(float4*)(wr)     = *(const float4*)&sW[k * SAP + tx * 8];
            *(float4*)(wr + 4) = *(const float4*)&sW[k * SAP + tx * 8 + 4];
#pragma unroll
            for (int i = 0; i < 8; i++)
#pragma unroll
                for (int j = 0; j < 8; j++)
                    acc[i][j] += a[i] * wr[j];
        }
        __syncthreads();
    }

#pragma unroll
    for (int i = 0; i < 8; i++) {
        int m = br + ty * 8 + i;
        if (m < M) {
            float* op = g_fp + (size_t)m * D + tx * 8;
            *(float4*)(op)     = *(const float4*)&acc[i][0];
            *(float4*)(op + 4) = *(const float4*)&acc[i][4];
        }
    }
}

// ---------------------------------------------------------------------------
// Aggregate + epilogue: one warp per node; per edge one broadcast int2 load
// (sequential within bin) + one 512B row gather.  4-way unroll.
// out[n] = relu(sum w_e * F'[src_e] + b)
// ---------------------------------------------------------------------------
__global__ void aggregate_out_kernel(const float* __restrict__ bias,
                                     float* __restrict__ out,
                                     int N) {
    int t = blockIdx.x * blockDim.x + threadIdx.x;
    int n = t >> 5;
    if (n >= N) return;
    int lane = t & 31;

    int beg = g_start[n];
    int end = g_start[n + 1];

    float4 acc = make_float4(0.f, 0.f, 0.f, 0.f);
    int i = beg;
    for (; i + 3 < end; i += 4) {
        int2 p0 = __ldg(&g_edges[i]);
        int2 p1 = __ldg(&g_edges[i + 1]);
        int2 p2 = __ldg(&g_edges[i + 2]);
        int2 p3 = __ldg(&g_edges[i + 3]);
        float w0 = __int_as_float(p0.y);
        float w1 = __int_as_float(p1.y);
        float w2 = __int_as_float(p2.y);
        float w3 = __int_as_float(p3.y);
        float4 v0 = *(const float4*)(g_fp + (size_t)p0.x * D + lane * 4);
        float4 v1 = *(const float4*)(g_fp + (size_t)p1.x * D + lane * 4);
        float4 v2 = *(const float4*)(g_fp + (size_t)p2.x * D + lane * 4);
        float4 v3 = *(const float4*)(g_fp + (size_t)p3.x * D + lane * 4);
        acc.x += v0.x * w0 + v1.x * w1 + v2.x * w2 + v3.x * w3;
        acc.y += v0.y * w0 + v1.y * w1 + v2.y * w2 + v3.y * w3;
        acc.z += v0.z * w0 + v1.z * w1 + v2.z * w2 + v3.z * w3;
        acc.w += v0.w * w0 + v1.w * w1 + v2.w * w2 + v3.w * w3;
    }
    for (; i < end; i++) {
        int2 p0 = __ldg(&g_edges[i]);
        float w0 = __int_as_float(p0.y);
        float4 v0 = *(const float4*)(g_fp + (size_t)p0.x * D + lane * 4);
        acc.x += v0.x * w0;
        acc.y += v0.y * w0;
        acc.z += v0.z * w0;
        acc.w += v0.w * w0;
    }

    float4 b4 = __ldg((const float4*)(bias + lane * 4));
    acc.x = fmaxf(acc.x + b4.x, 0.f);
    acc.y = fmaxf(acc.y + b4.y, 0.f);
    acc.z = fmaxf(acc.z + b4.z, 0.f);
    acc.w = fmaxf(acc.w + b4.w, 0.f);

    *(float4*)(out + (size_t)n * D + lane * 4) = acc;
}

// ---------------------------------------------------------------------------
// Launch: graph fork-join.  GEMM (feature-only) runs on a side stream,
// concurrent with the binning chain; join before aggregate.
// ---------------------------------------------------------------------------
extern "C" void kernel_launch(void* const* d_in, const int* in_sizes, int n_in,
                              void* d_out, int out_size) {
    const float* feature = (const float*)d_in[0];
    const int*   src     = (const int*)d_in[1];
    const int*   dst     = (const int*)d_in[2];
    const float* w       = (const float*)d_in[3];
    const float* Wm      = (const float*)d_in[4];
    const float* bias    = (const float*)d_in[5];
    float*       out     = (float*)d_out;

    int M = in_sizes[0] / D;
    int E = in_sizes[1];
    if (E > MAX_E) E = MAX_E;

    // One-time host-side resources (streams/events are not device memory).
    static cudaStream_t s2 = nullptr;
    static cudaEvent_t evFork = nullptr, evGemm = nullptr;
    if (s2 == nullptr) {
        cudaStreamCreateWithFlags(&s2, cudaStreamNonBlocking);
        cudaEventCreateWithFlags(&evFork, cudaEventDisableTiming);
        cudaEventCreateWithFlags(&evGemm, cudaEventDisableTiming);
    }

    // Fork: GEMM on side stream
    cudaEventRecord(evFork, 0);
    cudaStreamWaitEvent(s2, evFork, 0);
    gemm_kernel<<<(M + 127) / 128, 256, 0, s2>>>(feature, Wm, M);
    cudaEventRecord(evGemm, s2);

    // Main stream: binning chain (depends only on src/dst/w)
    zero_count_kernel<<<(M + 255) / 256, 256>>>(M);
    hist_kernel<<<(E + 255) / 256, 256>>>(dst, E);
    scan_kernel<<<1, 1024>>>(M);
    permute_kernel<<<(E + 255) / 256, 256>>>(src, dst, w, E);

    // Join, then aggregate + epilogue
    cudaStreamWaitEvent(0, evGemm, 0);
    long long agg_threads = (long long)M * 32;
    aggregate_out_kernel<<<(int)((agg_threads + 255) / 256), 256>>>(bias, out, M);
}

// round 8
// speedup vs baseline: 2.5072x; 2.5072x over previous
#include <cuda_runtime.h>

#define D 128
#define MAX_NODES 50048
#define MAX_E     1048576
#define BK 32
#define SAP 132
#define SCAN_B 256            // elements per scan block
#define MAX_SCAN_BLOCKS 256   // supports up to 65536 nodes

// Scratch (allocation-free rule: __device__ globals)
__device__ float g_fp[MAX_NODES * D];      // F' = feature @ W^T
__device__ int   g_count[MAX_NODES];
__device__ int   g_excl[MAX_NODES];        // block-local exclusive prescan
__device__ int   g_bsum[MAX_SCAN_BLOCKS];  // per-block totals
__device__ int   g_boff[MAX_SCAN_BLOCKS];  // scanned block offsets
__device__ int   g_start[MAX_NODES + 1];
__device__ int   g_cursor[MAX_NODES];
__device__ int2  g_edges[MAX_E];           // packed {src, w_bits} binned by dst

// ---------------------------------------------------------------------------
// zero per-node edge counts
// ---------------------------------------------------------------------------
__global__ void zero_count_kernel(int N) {
    int i = blockIdx.x * blockDim.x + threadIdx.x;
    if (i < N) g_count[i] = 0;
}

// ---------------------------------------------------------------------------
// histogram of dst (1 edge/thread, coalesced)
// ---------------------------------------------------------------------------
__global__ void hist_kernel(const int* __restrict__ dst, int E) {
    int e = blockIdx.x * blockDim.x + threadIdx.x;
    if (e < E) atomicAdd(&g_count[dst[e]], 1);
}

// ---------------------------------------------------------------------------
// scan stage 1: per-block (256 elems) exclusive scan, coalesced; block totals
// ---------------------------------------------------------------------------
__global__ void scan1_kernel(int N) {
    __shared__ int sh[SCAN_B];
    int t = threadIdx.x;
    int i = blockIdx.x * SCAN_B + t;
    int v = (i < N) ? g_count[i] : 0;
    sh[t] = v;
    __syncthreads();
#pragma unroll
    for (int off = 1; off < SCAN_B; off <<= 1) {
        int u = (t >= off) ? sh[t - off] : 0;
        __syncthreads();
        sh[t] += u;
        __syncthreads();
    }
    if (i < N) g_excl[i] = sh[t] - v;      // exclusive within block
    if (t == SCAN_B - 1) g_bsum[blockIdx.x] = sh[SCAN_B - 1];
}

// ---------------------------------------------------------------------------
// scan stage 2: single small block scans the per-block totals (<=256 of them)
// ---------------------------------------------------------------------------
__global__ void scan2_kernel(int NB, int N) {
    __shared__ int sh[MAX_SCAN_BLOCKS];
    int t = threadIdx.x;
    int v = (t < NB) ? g_bsum[t] : 0;
    sh[t] = v;
    __syncthreads();
#pragma unroll
    for (int off = 1; off < MAX_SCAN_BLOCKS; off <<= 1) {
        int u = (t >= off) ? sh[t - off] : 0;
        __syncthreads();
        sh[t] += u;
        __syncthreads();
    }
    if (t < NB) g_boff[t] = sh[t] - v;     // exclusive block offset
    if (t == MAX_SCAN_BLOCKS - 1) g_start[N] = sh[MAX_SCAN_BLOCKS - 1];  // total E
}

// ---------------------------------------------------------------------------
// scan stage 3: finalize g_start / g_cursor
// ---------------------------------------------------------------------------
__global__ void scan3_kernel(int N) {
    int i = blockIdx.x * blockDim.x + threadIdx.x;
    if (i < N) {
        int s = g_excl[i] + g_boff[i >> 8];   // SCAN_B == 256
        g_start[i]  = s;
        g_cursor[i] = s;
    }
}

// ---------------------------------------------------------------------------
// permute: write packed {src, w} into dst-ordered bins
// ---------------------------------------------------------------------------
__global__ void permute_kernel(const int* __restrict__ src,
                               const int* __restrict__ dst,
                               const float* __restrict__ w,
                               int E) {
    int e = blockIdx.x * blockDim.x + threadIdx.x;
    if (e < E) {
        int pos = atomicAdd(&g_cursor[dst[e]], 1);
        g_edges[pos] = make_int2(src[e], __float_as_int(w[e]));
    }
}

// ---------------------------------------------------------------------------
// GEMM: g_fp = feature @ W^T  (fp32 SIMT, 8x8 microtile) — side stream,
// concurrent with the binning chain.
// ---------------------------------------------------------------------------
__global__ void gemm_kernel(const float* __restrict__ A,
                            const float* __restrict__ Wm,
                            int M) {
    __shared__ float sA[BK * SAP];
    __shared__ float sW[BK * SAP];

    int tid = threadIdx.x;
    int tx = tid & 15;
    int ty = tid >> 4;
    int br = blockIdx.x * 128;

    float acc[8][8];
#pragma unroll
    for (int i = 0; i < 8; i++)
#pragma unroll
        for (int j = 0; j < 8; j++) acc[i][j] = 0.f;

    for (int kt = 0; kt < D; kt += BK) {
#pragma unroll
        for (int it = 0; it < 4; it++) {
            int idx4 = tid + it * 256;
            int m  = idx4 >> 3;
            int k  = (idx4 & 7) * 4;

            float4 va = make_float4(0.f, 0.f, 0.f, 0.f);
            if (br + m < M)
                va = *(const float4*)(A + (size_t)(br + m) * D + kt + k);
            sA[(k + 0) * SAP + m] = va.x;
            sA[(k + 1) * SAP + m] = va.y;
            sA[(k + 2) * SAP + m] = va.z;
            sA[(k + 3) * SAP + m] = va.w;

            float4 vw = *(const float4*)(Wm + m * D + kt + k);
            sW[(k + 0) * SAP + m] = vw.x;
            sW[(k + 1) * SAP + m] = vw.y;
            sW[(k + 2) * SAP + m] = vw.z;
            sW[(k + 3) * SAP + m] = vw.w;
        }
        __syncthreads();

#pragma unroll
        for (int k = 0; k < BK; k++) {
            float a[8], wr[8];
            *(float4*)(a)      = *(const float4*)&sA[k * SAP + ty * 8];
            *(float4*)(a + 4)  = *(const float4*)&sA[k * SAP + ty * 8 + 4];
            *(float4*)(wr)     = *(const float4*)&sW[k * SAP + tx * 8];
            *(float4*)(wr + 4) = *(const float4*)&sW[k * SAP + tx * 8 + 4];
#pragma unroll
            for (int i = 0; i < 8; i++)
#pragma unroll
                for (int j = 0; j < 8; j++)
                    acc[i][j] += a[i] * wr[j];
        }
        __syncthreads();
    }

#pragma unroll
    for (int i = 0; i < 8; i++) {
        int m = br + ty * 8 + i;
        if (m < M) {
            float* op = g_fp + (size_t)m * D + tx * 8;
            *(float4*)(op)     = *(const float4*)&acc[i][0];
            *(float4*)(op + 4) = *(const float4*)&acc[i][4];
        }
    }
}

// ---------------------------------------------------------------------------
// Aggregate + epilogue: one warp per node; per edge one broadcast int2 load +
// one 512B row gather.  out[n] = relu(sum w_e * F'[src_e] + b)
// ---------------------------------------------------------------------------
__global__ void aggregate_out_kernel(const float* __restrict__ bias,
                                     float* __restrict__ out,
                                     int N) {
    int t = blockIdx.x * blockDim.x + threadIdx.x;
    int n = t >> 5;
    if (n >= N) return;
    int lane = t & 31;

    int beg = g_start[n];
    int end = g_start[n + 1];

    float4 acc = make_float4(0.f, 0.f, 0.f, 0.f);
    int i = beg;
    for (; i + 3 < end; i += 4) {
        int2 p0 = __ldg(&g_edges[i]);
        int2 p1 = __ldg(&g_edges[i + 1]);
        int2 p2 = __ldg(&g_edges[i + 2]);
        int2 p3 = __ldg(&g_edges[i + 3]);
        float w0 = __int_as_float(p0.y);
        float w1 = __int_as_float(p1.y);
        float w2 = __int_as_float(p2.y);
        float w3 = __int_as_float(p3.y);
        float4 v0 = *(const float4*)(g_fp + (size_t)p0.x * D + lane * 4);
        float4 v1 = *(const float4*)(g_fp + (size_t)p1.x * D + lane * 4);
        float4 v2 = *(const float4*)(g_fp + (size_t)p2.x * D + lane * 4);
        float4 v3 = *(const float4*)(g_fp + (size_t)p3.x * D + lane * 4);
        acc.x += v0.x * w0 + v1.x * w1 + v2.x * w2 + v3.x * w3;
        acc.y += v0.y * w0 + v1.y * w1 + v2.y * w2 + v3.y * w3;
        acc.z += v0.z * w0 + v1.z * w1 + v2.z * w2 + v3.z * w3;
        acc.w += v0.w * w0 + v1.w * w1 + v2.w * w2 + v3.w * w3;
    }
    for (; i < end; i++) {
        int2 p0 = __ldg(&g_edges[i]);
        float w0 = __int_as_float(p0.y);
        float4 v0 = *(const float4*)(g_fp + (size_t)p0.x * D + lane * 4);
        acc.x += v0.x * w0;
        acc.y += v0.y * w0;
        acc.z += v0.z * w0;
        acc.w += v0.w * w0;
    }

    float4 b4 = __ldg((const float4*)(bias + lane * 4));
    acc.x = fmaxf(acc.x + b4.x, 0.f);
    acc.y = fmaxf(acc.y + b4.y, 0.f);
    acc.z = fmaxf(acc.z + b4.z, 0.f);
    acc.w = fmaxf(acc.w + b4.w, 0.f);

    *(float4*)(out + (size_t)n * D + lane * 4) = acc;
}

// ---------------------------------------------------------------------------
// Launch: graph fork-join.  GEMM on side stream, concurrent with the wide
// binning chain; join before aggregate.
// ---------------------------------------------------------------------------
extern "C" void kernel_launch(void* const* d_in, const int* in_sizes, int n_in,
                              void* d_out, int out_size) {
    const float* feature = (const float*)d_in[0];
    const int*   src     = (const int*)d_in[1];
    const int*   dst     = (const int*)d_in[2];
    const float* w       = (const float*)d_in[3];
    const float* Wm      = (const float*)d_in[4];
    const float* bias    = (const float*)d_in[5];
    float*       out     = (float*)d_out;

    int M = in_sizes[0] / D;
    int E = in_sizes[1];
    if (E > MAX_E) E = MAX_E;

    static cudaStream_t s2 = nullptr;
    static cudaEvent_t evFork = nullptr, evGemm = nullptr;
    if (s2 == nullptr) {
        cudaStreamCreateWithFlags(&s2, cudaStreamNonBlocking);
        cudaEventCreateWithFlags(&evFork, cudaEventDisableTiming);
        cudaEventCreateWithFlags(&evGemm, cudaEventDisableTiming);
    }

    // Fork: GEMM on side stream
    cudaEventRecord(evFork, 0);
    cudaStreamWaitEvent(s2, evFork, 0);
    gemm_kernel<<<(M + 127) / 128, 256, 0, s2>>>(feature, Wm, M);
    cudaEventRecord(evGemm, s2);

    // Main stream: binning chain (all wide kernels now)
    int NB = (M + SCAN_B - 1) / SCAN_B;   // <= 256 by MAX_NODES
    zero_count_kernel<<<(M + 255) / 256, 256>>>(M);
    hist_kernel<<<(E + 255) / 256, 256>>>(dst, E);
    scan1_kernel<<<NB, SCAN_B>>>(M);
    scan2_kernel<<<1, MAX_SCAN_BLOCKS>>>(NB, M);
    scan3_kernel<<<(M + 255) / 256, 256>>>(M);
    permute_kernel<<<(E + 255) / 256, 256>>>(src, dst, w, E);

    // Join, then aggregate + epilogue
    cudaStreamWaitEvent(0, evGemm, 0);
    long long agg_threads = (long long)M * 32;
    aggregate_out_kernel<<<(int)((agg_threads + 255) / 256), 256>>>(bias, out, M);
}